// round 16
// baseline (speedup 1.0000x reference)
#include <cuda_runtime.h>
#include <cuda_fp16.h>
#include <math.h>
#include <stdint.h>

#define NMAX 500000
#define NGROUPS 8
#define KT 27

// ---------------------------------------------------------------------------
// Device global scratch (no allocation allowed in kernel_launch)
// ---------------------------------------------------------------------------
__device__ __half g_xf16[(size_t)NMAX * 32];    // activations conv1, fp16 rows 64B
__device__ __half g_h1f16[(size_t)NMAX * 64];   // conv1 output (post-SiLU), rows 128B
__device__ __half g_skipf16[(size_t)NMAX * 64]; // skip path (fp16)
__device__ __half g_w1[KT * 64 * 32];           // [k][n][c]
__device__ __half g_w2[KT * 64 * 64];           // [k][n][c]
__device__ __half g_ws[64 * 32];                // Wskip transposed [n][c]
__device__ float g_bias1[64];
__device__ float g_bias2[64];
__device__ float g_stats1[16];                  // GN1 accumulation
__device__ float g_stats2[16];                  // GN2 accumulation

// ---------------------------------------------------------------------------
// Helpers
// ---------------------------------------------------------------------------
__device__ __forceinline__ uint32_t smem_to_u32(const void* p) {
    uint32_t a;
    asm("{ .reg .u64 t; cvta.to.shared.u64 t, %1; cvt.u32.u64 %0, t; }" : "=r"(a) : "l"(p));
    return a;
}
__device__ __forceinline__ void cp16(uint32_t dst, const void* src) {
    asm volatile("cp.async.cg.shared.global [%0], [%1], 16;" :: "r"(dst), "l"(src));
}
#define CP_COMMIT() asm volatile("cp.async.commit_group;" ::: "memory")
#define CP_WAIT(N) asm volatile("cp.async.wait_group %0;" :: "n"(N) : "memory")

__device__ __forceinline__ void ldsm4(uint32_t* r, uint32_t addr) {
    asm volatile("ldmatrix.sync.aligned.m8n8.x4.shared.b16 {%0,%1,%2,%3}, [%4];"
                 : "=r"(r[0]), "=r"(r[1]), "=r"(r[2]), "=r"(r[3]) : "r"(addr));
}
__device__ __forceinline__ void ldsm2(uint32_t* r, uint32_t addr) {
    asm volatile("ldmatrix.sync.aligned.m8n8.x2.shared.b16 {%0,%1}, [%2];"
                 : "=r"(r[0]), "=r"(r[1]) : "r"(addr));
}
__device__ __forceinline__ void mma16816(float* d, const uint32_t* a, const uint32_t* b) {
    asm volatile(
        "mma.sync.aligned.m16n8k16.row.col.f32.f16.f16.f32 "
        "{%0,%1,%2,%3}, {%4,%5,%6,%7}, {%8,%9}, {%0,%1,%2,%3};"
        : "+f"(d[0]), "+f"(d[1]), "+f"(d[2]), "+f"(d[3])
        : "r"(a[0]), "r"(a[1]), "r"(a[2]), "r"(a[3]), "r"(b[0]), "r"(b[1]));
}
__device__ __forceinline__ float silu_f(float t) { return t / (1.f + __expf(-t)); }

// ---------------------------------------------------------------------------
// Zero kernel (both stats arrays + both bias accumulators, once)
// ---------------------------------------------------------------------------
__global__ void zero_all_kernel() {
    int t = threadIdx.x;
    if (t < 16) g_stats1[t] = 0.f;
    if (t >= 16 && t < 32) g_stats2[t - 16] = 0.f;
    if (t >= 32 && t < 96) g_bias1[t - 32] = 0.f;
    if (t >= 96 && t < 160) g_bias2[t - 96] = 0.f;
}

// ---------------------------------------------------------------------------
// Fused: GN1 stats + fp32->fp16 conversion of x (single read pass)
// ---------------------------------------------------------------------------
__global__ void gn1_prep_kernel(const float* __restrict__ x, int n) {
    int tid = blockIdx.x * blockDim.x + threadIdx.x;
    int total = gridDim.x * blockDim.x;     // multiple of 4
    int q = tid & 3;
    float s0 = 0.f, ss0 = 0.f, s1 = 0.f, ss1 = 0.f;
    long nQ = (long)n * 4;
    for (long e = tid; e < nQ; e += total) {
        long v = e >> 2;
        const float4* src = (const float4*)(x + v * 32 + q * 8);
        float4 a = src[0], b = src[1];
        uint32_t w[4];
        __half2 h;
        h = __floats2half2_rn(a.x, a.y); w[0] = *(uint32_t*)&h;
        h = __floats2half2_rn(a.z, a.w); w[1] = *(uint32_t*)&h;
        h = __floats2half2_rn(b.x, b.y); w[2] = *(uint32_t*)&h;
        h = __floats2half2_rn(b.z, b.w); w[3] = *(uint32_t*)&h;
        *(uint4*)(g_xf16 + v * 32 + q * 8) = *(uint4*)w;
        s0 += (a.x + a.y) + (a.z + a.w);
        ss0 += a.x * a.x + a.y * a.y + a.z * a.z + a.w * a.w;
        s1 += (b.x + b.y) + (b.z + b.w);
        ss1 += b.x * b.x + b.y * b.y + b.z * b.z + b.w * b.w;
    }
    __shared__ float sh[16];
    if (threadIdx.x < 16) sh[threadIdx.x] = 0.f;
    __syncthreads();
    atomicAdd(&sh[4 * q + 0], s0);
    atomicAdd(&sh[4 * q + 1], ss0);
    atomicAdd(&sh[4 * q + 2], s1);
    atomicAdd(&sh[4 * q + 3], ss1);
    __syncthreads();
    if (threadIdx.x < 16) atomicAdd(&g_stats1[threadIdx.x], sh[threadIdx.x]);
}

// ---------------------------------------------------------------------------
// Weight prep with inline GN finalize.
// prepW1: grid KT+1; block KT handles the Wskip transpose instead.
// ---------------------------------------------------------------------------
__global__ void __launch_bounds__(256)
prepW1_kernel(const float* __restrict__ W1,
              const float* __restrict__ Wskip,
              const float* __restrict__ gamma,
              const float* __restrict__ beta, int n) {
    const int k = blockIdx.x;
    const int tid = threadIdx.x;
    const int nn = tid & 63;
    const int q = tid >> 6;

    if (k == KT) {   // Wskip [32][64] -> g_ws [n][c] fp16
        for (int c = q * 8; c < q * 8 + 8; ++c)
            g_ws[nn * 32 + c] = __float2half_rn(Wskip[(size_t)c * 64 + nn]);
        return;
    }

    __shared__ float ssc[32], sbi[32];
    if (tid < 32) {
        int c = tid;
        int g = c / 4;                      // 32 ch / 8 groups
        float cnt = (float)n * 4;
        float mean = g_stats1[2 * g] / cnt;
        float var = g_stats1[2 * g + 1] / cnt - mean * mean;
        float sc = gamma[c] * rsqrtf(var + 1e-5f);
        ssc[c] = sc;
        sbi[c] = beta[c] - mean * sc;
    }
    __syncthreads();

    float bs = 0.f;
    for (int c = q * 8; c < q * 8 + 8; ++c) {
        float w = W1[((size_t)(k * 32 + c)) * 64 + nn];
        bs += sbi[c] * w;
        g_w1[((size_t)(k * 64 + nn)) * 32 + c] = __float2half_rn(w * ssc[c]);
    }
    atomicAdd(&g_bias1[nn], bs);
}

__global__ void __launch_bounds__(256)
prepW2_kernel(const float* __restrict__ W2,
              const float* __restrict__ gamma,
              const float* __restrict__ beta, int n) {
    const int k = blockIdx.x;
    const int tid = threadIdx.x;
    const int nn = tid & 63;
    const int q = tid >> 6;

    __shared__ float ssc[64], sbi[64];
    if (tid < 64) {
        int c = tid;
        int g = c / 8;                      // 64 ch / 8 groups
        float cnt = (float)n * 8;
        float mean = g_stats2[2 * g] / cnt;
        float var = g_stats2[2 * g + 1] / cnt - mean * mean;
        float sc = gamma[c] * rsqrtf(var + 1e-5f);
        ssc[c] = sc;
        sbi[c] = beta[c] - mean * sc;
    }
    __syncthreads();

    float bs = 0.f;
    for (int c = q * 16; c < q * 16 + 16; ++c) {
        float w = W2[((size_t)(k * 64 + c)) * 64 + nn];
        bs += sbi[c] * w;
        g_w2[((size_t)(k * 64 + nn)) * 64 + c] = __float2half_rn(w * ssc[c]);
    }
    atomicAdd(&g_bias2[nn], bs);
}

// ---------------------------------------------------------------------------
// Skip path via MMA, multi-tile pipelined: each CTA does NTILE consecutive
// 256-voxel tiles with a 2-stage A buffer; B staged once.
// g_skipf16[v] = fp16(xf16[v] @ Ws + bskip)
// ---------------------------------------------------------------------------
#define SKIP_NTILE 4
__global__ void __launch_bounds__(256, 2)
skip_mma_kernel(const __half* __restrict__ Araw,   // g_xf16
                const __half* __restrict__ Bw,     // g_ws
                const float* __restrict__ obias,   // bskip
                int n, int ntiles) {
    extern __shared__ __align__(1024) char dsmem[];
    float* sbias = (float*)dsmem;
    const uint32_t Bb = smem_to_u32(dsmem + 1024);
    const uint32_t A0 = Bb + 4096u;        // two 16KB A stages

    const int tid = threadIdx.x;
    const int w = tid >> 5;
    const int lane = tid & 31;
    const int tile0 = blockIdx.x * SKIP_NTILE;

    if (tid < 64) sbias[tid] = obias[tid];

    auto load_A = [&](int tile, uint32_t Ab) {
        const int v0 = tile * 256;
        const int lastrow = n - 1 - v0;
        const int lrow = tid >> 2, lchk = tid & 3;
#pragma unroll
        for (int p = 0; p < 4; ++p) {
            int row = p * 64 + lrow;
            int vr = row < lastrow ? row : lastrow;
            cp16(Ab + (uint32_t)row * 64 +
                     (((uint32_t)lchk ^ ((uint32_t)row & 3)) << 4),
                 (const char*)Araw + ((size_t)(v0 + vr) * 32 + lchk * 8) * 2);
        }
    };

    // stage B once + first A tile
    {
        int q = tid;
        int row = q >> 2;
        uint32_t c = (uint32_t)(q & 3);
        cp16(Bb + (uint32_t)row * 64 + ((c ^ ((uint32_t)row & 3)) << 4),
             (const char*)Bw + (size_t)q * 16);
    }
    load_A(tile0, A0);
    CP_COMMIT();

    const uint32_t asel = (uint32_t)(lane >> 4);
    const int brow = lane & 7;
    const uint32_t bsel = (uint32_t)((lane >> 3) & 1);
    const int arow0 = w * 32 + (lane & 15);
    const int g = lane >> 2, tg = lane & 3;

    for (int t = 0; t < SKIP_NTILE; ++t) {
        const int tile = tile0 + t;
        if (tile >= ntiles) break;
        if (tile + 1 < ntiles && t + 1 < SKIP_NTILE) {
            load_A(tile + 1, A0 + (uint32_t)((t + 1) & 1) * 16384u);
            CP_COMMIT();
            CP_WAIT(1);
        } else {
            CP_WAIT(0);
        }
        __syncthreads();
        const uint32_t Ab = A0 + (uint32_t)(t & 1) * 16384u;

        float acc[2][8][4];
#pragma unroll
        for (int s = 0; s < 2; ++s)
#pragma unroll
            for (int i = 0; i < 8; ++i)
#pragma unroll
                for (int j = 0; j < 4; ++j) acc[s][i][j] = 0.f;

        uint32_t a[2][2][4];
#pragma unroll
        for (int s = 0; s < 2; ++s) {
            const int ar = arow0 + s * 16;
#pragma unroll
            for (int kc = 0; kc < 2; ++kc)
                ldsm4(a[s][kc], Ab + (uint32_t)ar * 64 +
                                ((((uint32_t)kc * 2 + asel) ^ ((uint32_t)ar & 3)) << 4));
        }
#pragma unroll
        for (int nt = 0; nt < 8; ++nt) {
#pragma unroll
            for (int kc = 0; kc < 2; ++kc) {
                uint32_t b2[2];
                ldsm2(b2, Bb + (uint32_t)nt * 512 + (uint32_t)brow * 64 +
                              ((((uint32_t)kc * 2 + bsel) ^ ((uint32_t)brow & 3)) << 4));
                mma16816(acc[0][nt], a[0][kc], b2);
                mma16816(acc[1][nt], a[1][kc], b2);
            }
        }

        const int v0 = tile * 256;
#pragma unroll
        for (int s = 0; s < 2; ++s) {
            const int row0 = v0 + w * 32 + s * 16 + g;
#pragma unroll
            for (int half = 0; half < 2; ++half) {
                int v = row0 + half * 8;
                if (v < n) {
                    __half* po = g_skipf16 + (size_t)v * 64;
#pragma unroll
                    for (int nt = 0; nt < 8; ++nt) {
                        int c = nt * 8 + tg * 2;
                        __half2 hh = __floats2half2_rn(
                            acc[s][nt][half * 2 + 0] + sbias[c],
                            acc[s][nt][half * 2 + 1] + sbias[c + 1]);
                        *(uint32_t*)(po + c) = *(uint32_t*)&hh;
                    }
                }
            }
        }
        __syncthreads();   // stage (t&1) free before it is reloaded at t+1
    }
}

// ---------------------------------------------------------------------------
// mma.sync gather-conv (proven R13/R14): fp16 x fp16, SMEM index block staged
// straight from nbr [v][k]; warp m32 x n64.
// CONV2=false: CIN=32, 4-stage distance-2; out fp16; GN2 stats in epilogue.
// CONV2=true : CIN=64, 2-stage; out fp32 = silu(conv)+skip.
// ---------------------------------------------------------------------------
template <bool CONV2>
__global__ void __launch_bounds__(256, 2)
mma_conv_kernel(const __half* __restrict__ Araw,
                const int* __restrict__ nbr,    // original [v][KT]
                const __half* __restrict__ Bw,
                const float* __restrict__ biasv,
                const __half* __restrict__ skipf,  // conv2 only
                void* __restrict__ outp, int n) {
    constexpr uint32_t IDX_BYTES = 28672u;                 // >= 1729*16, padded
    constexpr uint32_t A_BYTES = CONV2 ? 32768u : 16384u;  // 256 rows
    constexpr uint32_t B_BYTES = CONV2 ? 8192u : 4096u;    // 64 rows
    constexpr uint32_t STRIDE = A_BYTES + B_BYTES;
    constexpr int NSTAGE = CONV2 ? 2 : 4;
    constexpr int NCHUNK = (256 * KT) / 4 + 1;             // 1729

    extern __shared__ __align__(1024) char dsmem[];
    float* sbias = (float*)dsmem;
    float* shst = (float*)(dsmem + 512);     // GN2 stats staging (16 floats)
    int* sidxw = (int*)(dsmem + 1024);
    const uint32_t idxb = smem_to_u32(dsmem + 1024);
    const uint32_t base0 = idxb + IDX_BYTES;

    const int tid = threadIdx.x;
    const int w = tid >> 5;
    const int lane = tid & 31;
    const int v0 = blockIdx.x * 256;
    const int lastrow = n - 1 - v0;          // >= 0; >= 255 for full CTAs

    if (tid < 64) sbias[tid] = biasv[tid];
    if constexpr (!CONV2) {
        if (tid < 16) shst[tid] = 0.f;
    }

    // ---- stage index block straight from nbr (contiguous in [v][k]) ----
    const int base_int = (v0 * KT) & ~3;     // 16B-aligned start
    const int ofs = v0 * KT - base_int;      // 0..3
    {
        const int total_ints = n * KT;
#pragma unroll
        for (int j = 0; j < 7; ++j) {
            int c = tid + j * 256;
            if (c < NCHUNK) {
                int gi = base_int + c * 4;
                if (gi + 4 <= total_ints) {
                    cp16(idxb + (uint32_t)c * 16, nbr + gi);
                } else {
#pragma unroll
                    for (int t = 0; t < 4; ++t) {
                        int g2 = gi + t;
                        sidxw[c * 4 + t] = (g2 < total_ints) ? nbr[g2] : 0;
                    }
                }
            }
        }
        CP_COMMIT();
        CP_WAIT(0);
        __syncthreads();
    }
    const int* si = sidxw + ofs;

    // fragment address components
    const uint32_t asel = (uint32_t)(lane >> 4);        // k-chunk low/high 8
    const int brow = lane & 7;
    const uint32_t bsel = (uint32_t)((lane >> 3) & 1);
    const int arow0 = w * 32 + (lane & 15);             // slab 0 row; slab1 = +16

    float acc[2][8][4];
#pragma unroll
    for (int s = 0; s < 2; ++s)
#pragma unroll
        for (int i = 0; i < 8; ++i)
#pragma unroll
            for (int j = 0; j < 4; ++j) acc[s][i][j] = 0.f;

    // stage loader: consecutive lanes cover one row's 16B chunks;
    // index = si[min(row, lastrow)*KT + k] (tail clamped)
    auto load_tap = [&](int k, uint32_t stage) {
        if constexpr (CONV2) {
            const int lrow = tid >> 3, lchk = tid & 7;   // 32 rows/pass, 8 passes
#pragma unroll
            for (int p = 0; p < 8; ++p) {
                int row = p * 32 + lrow;
                int vr = row < lastrow ? row : lastrow;
                int idx = si[vr * KT + k];
                cp16(stage + (uint32_t)row * 128 +
                         (((uint32_t)lchk ^ ((uint32_t)row & 7)) << 4),
                     (const char*)Araw + (size_t)idx * 128 + lchk * 16);
            }
#pragma unroll
            for (int j = 0; j < 2; ++j) {
                int q = tid + j * 256;               // 512 chunks of 16B
                int row = q >> 3;
                uint32_t c = (uint32_t)(q & 7);
                cp16(stage + A_BYTES + (uint32_t)row * 128 +
                         ((c ^ ((uint32_t)row & 7)) << 4),
                     (const char*)Bw + (size_t)k * 8192 + (size_t)q * 16);
            }
        } else {
            const int lrow = tid >> 2, lchk = tid & 3;   // 64 rows/pass, 4 passes
#pragma unroll
            for (int p = 0; p < 4; ++p) {
                int row = p * 64 + lrow;
                int vr = row < lastrow ? row : lastrow;
                int idx = si[vr * KT + k];
                cp16(stage + (uint32_t)row * 64 +
                         (((uint32_t)lchk ^ ((uint32_t)row & 3)) << 4),
                     (const char*)Araw + (size_t)idx * 64 + lchk * 16);
            }
            {
                int q = tid;                          // 256 chunks of 16B
                int row = q >> 2;
                uint32_t c = (uint32_t)(q & 3);
                cp16(stage + A_BYTES + (uint32_t)row * 64 +
                         ((c ^ ((uint32_t)row & 3)) << 4),
                     (const char*)Bw + (size_t)k * 4096 + (size_t)q * 16);
            }
        }
    };

    // prologue
    if constexpr (CONV2) {
        load_tap(0, base0);
        CP_COMMIT();
    } else {
        load_tap(0, base0);
        CP_COMMIT();
        load_tap(1, base0 + STRIDE);
        CP_COMMIT();
    }

    for (int k = 0; k < KT; ++k) {
        if constexpr (CONV2) {
            __syncthreads();
            if (k + 1 < KT) {
                load_tap(k + 1, base0 + (uint32_t)((k + 1) & 1) * STRIDE);
                CP_COMMIT();
                CP_WAIT(1);
            } else {
                CP_WAIT(0);
            }
            __syncthreads();
        } else {
            if (k + 2 < KT) {
                load_tap(k + 2, base0 + (uint32_t)((k + 2) & 3) * STRIDE);
                CP_COMMIT();
                CP_WAIT(2);
            } else if (k + 1 < KT) {
                CP_WAIT(1);
            } else {
                CP_WAIT(0);
            }
            __syncthreads();
        }
        const uint32_t Ab = base0 + (uint32_t)(k % NSTAGE) * STRIDE;
        const uint32_t Bb = Ab + A_BYTES;
        if constexpr (CONV2) {
            uint32_t a[2][4][4];
#pragma unroll
            for (int s = 0; s < 2; ++s) {
                const int ar = arow0 + s * 16;
#pragma unroll
                for (int kc = 0; kc < 4; ++kc)
                    ldsm4(a[s][kc], Ab + (uint32_t)ar * 128 +
                                    ((((uint32_t)kc * 2 + asel) ^ ((uint32_t)ar & 7)) << 4));
            }
#pragma unroll
            for (int nt = 0; nt < 8; ++nt) {
#pragma unroll
                for (int kc = 0; kc < 4; ++kc) {
                    uint32_t b2[2];
                    ldsm2(b2, Bb + (uint32_t)nt * 1024 + (uint32_t)brow * 128 +
                                  ((((uint32_t)kc * 2 + bsel) ^ ((uint32_t)brow & 7)) << 4));
                    mma16816(acc[0][nt], a[0][kc], b2);
                    mma16816(acc[1][nt], a[1][kc], b2);
                }
            }
        } else {
            uint32_t a[2][2][4];
#pragma unroll
            for (int s = 0; s < 2; ++s) {
                const int ar = arow0 + s * 16;
#pragma unroll
                for (int kc = 0; kc < 2; ++kc)
                    ldsm4(a[s][kc], Ab + (uint32_t)ar * 64 +
                                    ((((uint32_t)kc * 2 + asel) ^ ((uint32_t)ar & 3)) << 4));
            }
#pragma unroll
            for (int nt = 0; nt < 8; ++nt) {
#pragma unroll
                for (int kc = 0; kc < 2; ++kc) {
                    uint32_t b2[2];
                    ldsm2(b2, Bb + (uint32_t)nt * 512 + (uint32_t)brow * 64 +
                                  ((((uint32_t)kc * 2 + bsel) ^ ((uint32_t)brow & 3)) << 4));
                    mma16816(acc[0][nt], a[0][kc], b2);
                    mma16816(acc[1][nt], a[1][kc], b2);
                }
            }
        }
    }

    // ---- epilogue ----
    const int g = lane >> 2, tg = lane & 3;
    float ls[8], lss[8];
    if constexpr (!CONV2) {
#pragma unroll
        for (int nt = 0; nt < 8; ++nt) { ls[nt] = 0.f; lss[nt] = 0.f; }
    }
#pragma unroll
    for (int s = 0; s < 2; ++s) {
        const int row0 = v0 + w * 32 + s * 16 + g;
#pragma unroll
        for (int half = 0; half < 2; ++half) {
            int v = row0 + half * 8;
            if (v < n) {
                if constexpr (CONV2) {
                    float* po = (float*)outp + (size_t)v * 64;
                    const __half* sk = skipf + (size_t)v * 64;
#pragma unroll
                    for (int nt = 0; nt < 8; ++nt) {
                        int c = nt * 8 + tg * 2;
                        __half2 s2 = *(const __half2*)(sk + c);
                        float2 skf = __half22float2(s2);
                        float2 rr;
                        rr.x = silu_f(acc[s][nt][half * 2 + 0] + sbias[c]) + skf.x;
                        rr.y = silu_f(acc[s][nt][half * 2 + 1] + sbias[c + 1]) + skf.y;
                        *(float2*)(po + c) = rr;
                    }
                } else {
                    char* basep = (char*)outp + (size_t)v * 128;
#pragma unroll
                    for (int nt = 0; nt < 8; ++nt) {
                        int c = nt * 8 + tg * 2;
                        float f0 = silu_f(acc[s][nt][half * 2 + 0] + sbias[c]);
                        float f1 = silu_f(acc[s][nt][half * 2 + 1] + sbias[c + 1]);
                        __half2 hh = __floats2half2_rn(f0, f1);
                        *(uint32_t*)(basep + c * 2) = *(uint32_t*)&hh;
                        ls[nt] += f0 + f1;
                        lss[nt] += f0 * f0 + f1 * f1;
                    }
                }
            }
        }
    }
    if constexpr (!CONV2) {
#pragma unroll
        for (int nt = 0; nt < 8; ++nt) {
#pragma unroll
            for (int o = 16; o > 0; o >>= 1) {
                ls[nt] += __shfl_xor_sync(0xFFFFFFFFu, ls[nt], o);
                lss[nt] += __shfl_xor_sync(0xFFFFFFFFu, lss[nt], o);
            }
        }
        if (lane == 0) {
#pragma unroll
            for (int nt = 0; nt < 8; ++nt) {
                atomicAdd(&shst[2 * nt], ls[nt]);
                atomicAdd(&shst[2 * nt + 1], lss[nt]);
            }
        }
        __syncthreads();
        if (tid < 16) atomicAdd(&g_stats2[tid], shst[tid]);
    }
}

__global__ void fill_tail_kernel(float* out, long start, long end) {
    long i = start + (long)blockIdx.x * blockDim.x + threadIdx.x;
    if (i < end) out[i] = 0.f;
}

// ---------------------------------------------------------------------------
extern "C" void kernel_launch(void* const* d_in, const int* in_sizes, int n_in,
                              void* d_out, int out_size) {
    const float* x      = (const float*)d_in[0];
    const int*   nbr    = (const int*)d_in[1];
    const float* gamma1 = (const float*)d_in[2];
    const float* beta1  = (const float*)d_in[3];
    const float* W1     = (const float*)d_in[4];
    const float* gamma2 = (const float*)d_in[5];
    const float* beta2  = (const float*)d_in[6];
    const float* W2     = (const float*)d_in[7];
    const float* Wskip  = (const float*)d_in[8];
    const float* bskip  = (const float*)d_in[9];
    float* out = (float*)d_out;

    int n = in_sizes[0] / 32;
    int nblk_mma = (n + 255) / 256;
    int nblk_skip = (nblk_mma + SKIP_NTILE - 1) / SKIP_NTILE;

    __half *xf16p = nullptr, *h1p = nullptr, *skp = nullptr,
           *w1p = nullptr, *w2p = nullptr, *wsp = nullptr;
    float *b1p = nullptr, *b2p = nullptr;
    cudaGetSymbolAddress((void**)&xf16p, g_xf16);
    cudaGetSymbolAddress((void**)&h1p, g_h1f16);
    cudaGetSymbolAddress((void**)&skp, g_skipf16);
    cudaGetSymbolAddress((void**)&w1p, g_w1);
    cudaGetSymbolAddress((void**)&w2p, g_w2);
    cudaGetSymbolAddress((void**)&wsp, g_ws);
    cudaGetSymbolAddress((void**)&b1p, g_bias1);
    cudaGetSymbolAddress((void**)&b2p, g_bias2);

    const int IDXB = 28672;
    const int SMEM1 = 1024 + IDXB + 4 * (16384 + 4096);  // 111616
    const int SMEM2 = 1024 + IDXB + 2 * (32768 + 8192);  // 111616
    const int SMEMS = 1024 + 4096 + 2 * 16384;           // 37888
    cudaFuncSetAttribute(mma_conv_kernel<false>,
                         cudaFuncAttributeMaxDynamicSharedMemorySize, SMEM1);
    cudaFuncSetAttribute(mma_conv_kernel<true>,
                         cudaFuncAttributeMaxDynamicSharedMemorySize, SMEM2);
    cudaFuncSetAttribute(skip_mma_kernel,
                         cudaFuncAttributeMaxDynamicSharedMemorySize, SMEMS);

    // fused GN1 stats + x fp16 conversion (produces g_xf16 for skip too)
    zero_all_kernel<<<1, 160>>>();
    gn1_prep_kernel<<<1184, 256>>>(x, n);
    // W1 prep (inline GN1 finalize) + Wskip transpose (extra block)
    prepW1_kernel<<<KT + 1, 256>>>(W1, Wskip, gamma1, beta1, n);

    // skip path -> g_skipf16 (fp16, tensor cores, pipelined multi-tile)
    skip_mma_kernel<<<nblk_skip, 256, SMEMS>>>(xf16p, wsp, bskip, n, nblk_mma);

    // conv1 -> g_h1f16 (fp16, post-SiLU); epilogue accumulates GN2 stats
    mma_conv_kernel<false><<<nblk_mma, 256, SMEM1>>>(
        xf16p, nbr, w1p, b1p, nullptr, (void*)h1p, n);

    // W2 prep (inline GN2 finalize)
    prepW2_kernel<<<KT, 256>>>(W2, gamma2, beta2, n);

    // conv2 -> out = silu(conv2) + skip
    mma_conv_kernel<true><<<nblk_mma, 256, SMEM2>>>(
        h1p, nbr, w2p, b2p, skp, (void*)out, n);

    long main_elems = (long)n * 64;
    if ((long)out_size > main_elems) {
        long tail = (long)out_size - main_elems;
        int tb = (int)((tail + 255) / 256);
        fill_tail_kernel<<<tb, 256>>>(out, main_elems, (long)out_size);
    }
}

// round 17
// speedup vs baseline: 1.0182x; 1.0182x over previous
#include <cuda_runtime.h>
#include <cuda_fp16.h>
#include <math.h>
#include <stdint.h>

#define NMAX 500000
#define NGROUPS 8
#define KT 27

// ---------------------------------------------------------------------------
// Device global scratch (no allocation allowed in kernel_launch)
// ---------------------------------------------------------------------------
__device__ __half g_xf16[(size_t)NMAX * 32];    // activations conv1, fp16 rows 64B
__device__ __half g_h1f16[(size_t)NMAX * 64];   // conv1 output (post-SiLU), rows 128B
__device__ __half g_skipf16[(size_t)NMAX * 64]; // skip path (fp16)
__device__ __half g_w1[KT * 64 * 32];           // [k][n][c]
__device__ __half g_w2[KT * 64 * 64];           // [k][n][c]
__device__ __half g_ws[64 * 32];                // Wskip transposed [n][c]
__device__ float g_bias1[64];
__device__ float g_bias2[64];
__device__ float g_stats1[16];                  // GN1 accumulation
__device__ float g_stats2[16];                  // GN2 accumulation

// ---------------------------------------------------------------------------
// Helpers
// ---------------------------------------------------------------------------
__device__ __forceinline__ uint32_t smem_to_u32(const void* p) {
    uint32_t a;
    asm("{ .reg .u64 t; cvta.to.shared.u64 t, %1; cvt.u32.u64 %0, t; }" : "=r"(a) : "l"(p));
    return a;
}
__device__ __forceinline__ void cp16(uint32_t dst, const void* src) {
    asm volatile("cp.async.cg.shared.global [%0], [%1], 16;" :: "r"(dst), "l"(src));
}
#define CP_COMMIT() asm volatile("cp.async.commit_group;" ::: "memory")
#define CP_WAIT(N) asm volatile("cp.async.wait_group %0;" :: "n"(N) : "memory")

__device__ __forceinline__ void ldsm4(uint32_t* r, uint32_t addr) {
    asm volatile("ldmatrix.sync.aligned.m8n8.x4.shared.b16 {%0,%1,%2,%3}, [%4];"
                 : "=r"(r[0]), "=r"(r[1]), "=r"(r[2]), "=r"(r[3]) : "r"(addr));
}
__device__ __forceinline__ void ldsm2(uint32_t* r, uint32_t addr) {
    asm volatile("ldmatrix.sync.aligned.m8n8.x2.shared.b16 {%0,%1}, [%2];"
                 : "=r"(r[0]), "=r"(r[1]) : "r"(addr));
}
__device__ __forceinline__ void mma16816(float* d, const uint32_t* a, const uint32_t* b) {
    asm volatile(
        "mma.sync.aligned.m16n8k16.row.col.f32.f16.f16.f32 "
        "{%0,%1,%2,%3}, {%4,%5,%6,%7}, {%8,%9}, {%0,%1,%2,%3};"
        : "+f"(d[0]), "+f"(d[1]), "+f"(d[2]), "+f"(d[3])
        : "r"(a[0]), "r"(a[1]), "r"(a[2]), "r"(a[3]), "r"(b[0]), "r"(b[1]));
}
__device__ __forceinline__ float silu_f(float t) { return t / (1.f + __expf(-t)); }

// ---------------------------------------------------------------------------
// Zero kernel (both stats arrays + both bias accumulators, once)
// ---------------------------------------------------------------------------
__global__ void zero_all_kernel() {
    int t = threadIdx.x;
    if (t < 16) g_stats1[t] = 0.f;
    if (t >= 16 && t < 32) g_stats2[t - 16] = 0.f;
    if (t >= 32 && t < 96) g_bias1[t - 32] = 0.f;
    if (t >= 96 && t < 160) g_bias2[t - 96] = 0.f;
}

// ---------------------------------------------------------------------------
// Fused: GN1 stats + fp32->fp16 conversion of x (single read pass)
// ---------------------------------------------------------------------------
__global__ void gn1_prep_kernel(const float* __restrict__ x, int n) {
    int tid = blockIdx.x * blockDim.x + threadIdx.x;
    int total = gridDim.x * blockDim.x;     // multiple of 4
    int q = tid & 3;
    float s0 = 0.f, ss0 = 0.f, s1 = 0.f, ss1 = 0.f;
    long nQ = (long)n * 4;
    for (long e = tid; e < nQ; e += total) {
        long v = e >> 2;
        const float4* src = (const float4*)(x + v * 32 + q * 8);
        float4 a = src[0], b = src[1];
        uint32_t w[4];
        __half2 h;
        h = __floats2half2_rn(a.x, a.y); w[0] = *(uint32_t*)&h;
        h = __floats2half2_rn(a.z, a.w); w[1] = *(uint32_t*)&h;
        h = __floats2half2_rn(b.x, b.y); w[2] = *(uint32_t*)&h;
        h = __floats2half2_rn(b.z, b.w); w[3] = *(uint32_t*)&h;
        *(uint4*)(g_xf16 + v * 32 + q * 8) = *(uint4*)w;
        s0 += (a.x + a.y) + (a.z + a.w);
        ss0 += a.x * a.x + a.y * a.y + a.z * a.z + a.w * a.w;
        s1 += (b.x + b.y) + (b.z + b.w);
        ss1 += b.x * b.x + b.y * b.y + b.z * b.z + b.w * b.w;
    }
    __shared__ float sh[16];
    if (threadIdx.x < 16) sh[threadIdx.x] = 0.f;
    __syncthreads();
    atomicAdd(&sh[4 * q + 0], s0);
    atomicAdd(&sh[4 * q + 1], ss0);
    atomicAdd(&sh[4 * q + 2], s1);
    atomicAdd(&sh[4 * q + 3], ss1);
    __syncthreads();
    if (threadIdx.x < 16) atomicAdd(&g_stats1[threadIdx.x], sh[threadIdx.x]);
}

// ---------------------------------------------------------------------------
// Weight prep with inline GN finalize.
// prepW1: grid KT+1; block KT handles the Wskip transpose instead.
// ---------------------------------------------------------------------------
__global__ void __launch_bounds__(256)
prepW1_kernel(const float* __restrict__ W1,
              const float* __restrict__ Wskip,
              const float* __restrict__ gamma,
              const float* __restrict__ beta, int n) {
    const int k = blockIdx.x;
    const int tid = threadIdx.x;
    const int nn = tid & 63;
    const int q = tid >> 6;

    if (k == KT) {   // Wskip [32][64] -> g_ws [n][c] fp16
        for (int c = q * 8; c < q * 8 + 8; ++c)
            g_ws[nn * 32 + c] = __float2half_rn(Wskip[(size_t)c * 64 + nn]);
        return;
    }

    __shared__ float ssc[32], sbi[32];
    if (tid < 32) {
        int c = tid;
        int g = c / 4;                      // 32 ch / 8 groups
        float cnt = (float)n * 4;
        float mean = g_stats1[2 * g] / cnt;
        float var = g_stats1[2 * g + 1] / cnt - mean * mean;
        float sc = gamma[c] * rsqrtf(var + 1e-5f);
        ssc[c] = sc;
        sbi[c] = beta[c] - mean * sc;
    }
    __syncthreads();

    float bs = 0.f;
    for (int c = q * 8; c < q * 8 + 8; ++c) {
        float w = W1[((size_t)(k * 32 + c)) * 64 + nn];
        bs += sbi[c] * w;
        g_w1[((size_t)(k * 64 + nn)) * 32 + c] = __float2half_rn(w * ssc[c]);
    }
    atomicAdd(&g_bias1[nn], bs);
}

__global__ void __launch_bounds__(256)
prepW2_kernel(const float* __restrict__ W2,
              const float* __restrict__ gamma,
              const float* __restrict__ beta, int n) {
    const int k = blockIdx.x;
    const int tid = threadIdx.x;
    const int nn = tid & 63;
    const int q = tid >> 6;

    __shared__ float ssc[64], sbi[64];
    if (tid < 64) {
        int c = tid;
        int g = c / 8;                      // 64 ch / 8 groups
        float cnt = (float)n * 8;
        float mean = g_stats2[2 * g] / cnt;
        float var = g_stats2[2 * g + 1] / cnt - mean * mean;
        float sc = gamma[c] * rsqrtf(var + 1e-5f);
        ssc[c] = sc;
        sbi[c] = beta[c] - mean * sc;
    }
    __syncthreads();

    float bs = 0.f;
    for (int c = q * 16; c < q * 16 + 16; ++c) {
        float w = W2[((size_t)(k * 64 + c)) * 64 + nn];
        bs += sbi[c] * w;
        g_w2[((size_t)(k * 64 + nn)) * 64 + c] = __float2half_rn(w * ssc[c]);
    }
    atomicAdd(&g_bias2[nn], bs);
}

// ---------------------------------------------------------------------------
// mma.sync gather-conv (proven R13-R15 core): fp16 x fp16, SMEM index block
// staged straight from nbr [v][k]; warp m32 x n64.
// CONV2=false: CIN=32, 4-stage distance-2; out fp16; GN2 stats in epilogue;
//              ALSO computes the skip path (own-row GEMM vs g_ws) fused:
//              skip loads issue after the main loop into the free stage 0
//              and fly under the h1 epilogue.
// CONV2=true : CIN=64, 2-stage; out fp32 = silu(conv)+skip.
// ---------------------------------------------------------------------------
template <bool CONV2>
__global__ void __launch_bounds__(256, 2)
mma_conv_kernel(const __half* __restrict__ Araw,
                const int* __restrict__ nbr,    // original [v][KT]
                const __half* __restrict__ Bw,
                const float* __restrict__ biasv,
                const __half* __restrict__ skipf,   // conv2: skip input
                const __half* __restrict__ wsb,     // conv1: g_ws
                const float* __restrict__ skipbias, // conv1: bskip
                void* __restrict__ outp, int n) {
    constexpr uint32_t IDX_BYTES = 28672u;                 // >= 1729*16, padded
    constexpr uint32_t A_BYTES = CONV2 ? 32768u : 16384u;  // 256 rows
    constexpr uint32_t B_BYTES = CONV2 ? 8192u : 4096u;    // 64 rows
    constexpr uint32_t STRIDE = A_BYTES + B_BYTES;
    constexpr int NSTAGE = CONV2 ? 2 : 4;
    constexpr int NCHUNK = (256 * KT) / 4 + 1;             // 1729

    extern __shared__ __align__(1024) char dsmem[];
    float* sbias = (float*)dsmem;            // 64 floats
    float* sskb = (float*)(dsmem + 256);     // 64 floats (conv1 skip bias)
    float* shst = (float*)(dsmem + 512);     // GN2 stats staging (16 floats)
    int* sidxw = (int*)(dsmem + 1024);
    const uint32_t idxb = smem_to_u32(dsmem + 1024);
    const uint32_t base0 = idxb + IDX_BYTES;

    const int tid = threadIdx.x;
    const int w = tid >> 5;
    const int lane = tid & 31;
    const int v0 = blockIdx.x * 256;
    const int lastrow = n - 1 - v0;          // >= 0; >= 255 for full CTAs

    if (tid < 64) sbias[tid] = biasv[tid];
    if constexpr (!CONV2) {
        if (tid < 16) shst[tid] = 0.f;
        if (tid >= 64 && tid < 128) sskb[tid - 64] = skipbias[tid - 64];
    }

    // ---- stage index block straight from nbr (contiguous in [v][k]) ----
    const int base_int = (v0 * KT) & ~3;     // 16B-aligned start
    const int ofs = v0 * KT - base_int;      // 0..3
    {
        const int total_ints = n * KT;
#pragma unroll
        for (int j = 0; j < 7; ++j) {
            int c = tid + j * 256;
            if (c < NCHUNK) {
                int gi = base_int + c * 4;
                if (gi + 4 <= total_ints) {
                    cp16(idxb + (uint32_t)c * 16, nbr + gi);
                } else {
#pragma unroll
                    for (int t = 0; t < 4; ++t) {
                        int g2 = gi + t;
                        sidxw[c * 4 + t] = (g2 < total_ints) ? nbr[g2] : 0;
                    }
                }
            }
        }
        CP_COMMIT();
        CP_WAIT(0);
        __syncthreads();
    }
    const int* si = sidxw + ofs;

    // fragment address components
    const uint32_t asel = (uint32_t)(lane >> 4);        // k-chunk low/high 8
    const int brow = lane & 7;
    const uint32_t bsel = (uint32_t)((lane >> 3) & 1);
    const int arow0 = w * 32 + (lane & 15);             // slab 0 row; slab1 = +16

    float acc[2][8][4];
#pragma unroll
    for (int s = 0; s < 2; ++s)
#pragma unroll
        for (int i = 0; i < 8; ++i)
#pragma unroll
            for (int j = 0; j < 4; ++j) acc[s][i][j] = 0.f;

    // stage loader: consecutive lanes cover one row's 16B chunks;
    // index = si[min(row, lastrow)*KT + k] (tail clamped)
    auto load_tap = [&](int k, uint32_t stage) {
        if constexpr (CONV2) {
            const int lrow = tid >> 3, lchk = tid & 7;   // 32 rows/pass, 8 passes
#pragma unroll
            for (int p = 0; p < 8; ++p) {
                int row = p * 32 + lrow;
                int vr = row < lastrow ? row : lastrow;
                int idx = si[vr * KT + k];
                cp16(stage + (uint32_t)row * 128 +
                         (((uint32_t)lchk ^ ((uint32_t)row & 7)) << 4),
                     (const char*)Araw + (size_t)idx * 128 + lchk * 16);
            }
#pragma unroll
            for (int j = 0; j < 2; ++j) {
                int q = tid + j * 256;               // 512 chunks of 16B
                int row = q >> 3;
                uint32_t c = (uint32_t)(q & 7);
                cp16(stage + A_BYTES + (uint32_t)row * 128 +
                         ((c ^ ((uint32_t)row & 7)) << 4),
                     (const char*)Bw + (size_t)k * 8192 + (size_t)q * 16);
            }
        } else {
            const int lrow = tid >> 2, lchk = tid & 3;   // 64 rows/pass, 4 passes
#pragma unroll
            for (int p = 0; p < 4; ++p) {
                int row = p * 64 + lrow;
                int vr = row < lastrow ? row : lastrow;
                int idx = si[vr * KT + k];
                cp16(stage + (uint32_t)row * 64 +
                         (((uint32_t)lchk ^ ((uint32_t)row & 3)) << 4),
                     (const char*)Araw + (size_t)idx * 64 + lchk * 16);
            }
            {
                int q = tid;                          // 256 chunks of 16B
                int row = q >> 2;
                uint32_t c = (uint32_t)(q & 3);
                cp16(stage + A_BYTES + (uint32_t)row * 64 +
                         ((c ^ ((uint32_t)row & 3)) << 4),
                     (const char*)Bw + (size_t)k * 4096 + (size_t)q * 16);
            }
        }
    };

    // prologue
    if constexpr (CONV2) {
        load_tap(0, base0);
        CP_COMMIT();
    } else {
        load_tap(0, base0);
        CP_COMMIT();
        load_tap(1, base0 + STRIDE);
        CP_COMMIT();
    }

    for (int k = 0; k < KT; ++k) {
        if constexpr (CONV2) {
            __syncthreads();
            if (k + 1 < KT) {
                load_tap(k + 1, base0 + (uint32_t)((k + 1) & 1) * STRIDE);
                CP_COMMIT();
                CP_WAIT(1);
            } else {
                CP_WAIT(0);
            }
            __syncthreads();
        } else {
            if (k + 2 < KT) {
                load_tap(k + 2, base0 + (uint32_t)((k + 2) & 3) * STRIDE);
                CP_COMMIT();
                CP_WAIT(2);
            } else if (k + 1 < KT) {
                CP_WAIT(1);
            } else {
                CP_WAIT(0);
            }
            __syncthreads();
        }
        const uint32_t Ab = base0 + (uint32_t)(k % NSTAGE) * STRIDE;
        const uint32_t Bb = Ab + A_BYTES;
        if constexpr (CONV2) {
            uint32_t a[2][4][4];
#pragma unroll
            for (int s = 0; s < 2; ++s) {
                const int ar = arow0 + s * 16;
#pragma unroll
                for (int kc = 0; kc < 4; ++kc)
                    ldsm4(a[s][kc], Ab + (uint32_t)ar * 128 +
                                    ((((uint32_t)kc * 2 + asel) ^ ((uint32_t)ar & 7)) << 4));
            }
#pragma unroll
            for (int nt = 0; nt < 8; ++nt) {
#pragma unroll
                for (int kc = 0; kc < 4; ++kc) {
                    uint32_t b2[2];
                    ldsm2(b2, Bb + (uint32_t)nt * 1024 + (uint32_t)brow * 128 +
                                  ((((uint32_t)kc * 2 + bsel) ^ ((uint32_t)brow & 7)) << 4));
                    mma16816(acc[0][nt], a[0][kc], b2);
                    mma16816(acc[1][nt], a[1][kc], b2);
                }
            }
        } else {
            uint32_t a[2][2][4];
#pragma unroll
            for (int s = 0; s < 2; ++s) {
                const int ar = arow0 + s * 16;
#pragma unroll
                for (int kc = 0; kc < 2; ++kc)
                    ldsm4(a[s][kc], Ab + (uint32_t)ar * 64 +
                                    ((((uint32_t)kc * 2 + asel) ^ ((uint32_t)ar & 3)) << 4));
            }
#pragma unroll
            for (int nt = 0; nt < 8; ++nt) {
#pragma unroll
                for (int kc = 0; kc < 2; ++kc) {
                    uint32_t b2[2];
                    ldsm2(b2, Bb + (uint32_t)nt * 512 + (uint32_t)brow * 64 +
                                  ((((uint32_t)kc * 2 + bsel) ^ ((uint32_t)brow & 3)) << 4));
                    mma16816(acc[0][nt], a[0][kc], b2);
                    mma16816(acc[1][nt], a[1][kc], b2);
                }
            }
        }
    }

    // ---- conv1: issue skip loads into stage 0 (free since tap 24; all
    // warps passed its compute at the k=25 barrier). Flies under epilogue.
    if constexpr (!CONV2) {
        const int lrow = tid >> 2, lchk = tid & 3;
#pragma unroll
        for (int p = 0; p < 4; ++p) {
            int row = p * 64 + lrow;
            int vr = row < lastrow ? row : lastrow;
            cp16(base0 + (uint32_t)row * 64 +
                     (((uint32_t)lchk ^ ((uint32_t)row & 3)) << 4),
                 (const char*)Araw + ((size_t)(v0 + vr) * 32 + lchk * 8) * 2);
        }
        {
            int q = tid, row = q >> 2;
            uint32_t c = (uint32_t)(q & 3);
            cp16(base0 + 16384u + (uint32_t)row * 64 +
                     ((c ^ ((uint32_t)row & 3)) << 4),
                 (const char*)wsb + (size_t)q * 16);
        }
        CP_COMMIT();
    }

    // ---- epilogue ----
    const int g = lane >> 2, tg = lane & 3;
    float ls[8], lss[8];
    if constexpr (!CONV2) {
#pragma unroll
        for (int nt = 0; nt < 8; ++nt) { ls[nt] = 0.f; lss[nt] = 0.f; }
    }
#pragma unroll
    for (int s = 0; s < 2; ++s) {
        const int row0 = v0 + w * 32 + s * 16 + g;
#pragma unroll
        for (int half = 0; half < 2; ++half) {
            int v = row0 + half * 8;
            if (v < n) {
                if constexpr (CONV2) {
                    float* po = (float*)outp + (size_t)v * 64;
                    const __half* sk = skipf + (size_t)v * 64;
#pragma unroll
                    for (int nt = 0; nt < 8; ++nt) {
                        int c = nt * 8 + tg * 2;
                        __half2 s2 = *(const __half2*)(sk + c);
                        float2 skf = __half22float2(s2);
                        float2 rr;
                        rr.x = silu_f(acc[s][nt][half * 2 + 0] + sbias[c]) + skf.x;
                        rr.y = silu_f(acc[s][nt][half * 2 + 1] + sbias[c + 1]) + skf.y;
                        *(float2*)(po + c) = rr;
                    }
                } else {
                    char* basep = (char*)outp + (size_t)v * 128;
#pragma unroll
                    for (int nt = 0; nt < 8; ++nt) {
                        int c = nt * 8 + tg * 2;
                        float f0 = silu_f(acc[s][nt][half * 2 + 0] + sbias[c]);
                        float f1 = silu_f(acc[s][nt][half * 2 + 1] + sbias[c + 1]);
                        __half2 hh = __floats2half2_rn(f0, f1);
                        *(uint32_t*)(basep + c * 2) = *(uint32_t*)&hh;
                        ls[nt] += f0 + f1;
                        lss[nt] += f0 * f0 + f1 * f1;
                    }
                }
            }
        }
    }
    if constexpr (!CONV2) {
#pragma unroll
        for (int nt = 0; nt < 8; ++nt) {
#pragma unroll
            for (int o = 16; o > 0; o >>= 1) {
                ls[nt] += __shfl_xor_sync(0xFFFFFFFFu, ls[nt], o);
                lss[nt] += __shfl_xor_sync(0xFFFFFFFFu, lss[nt], o);
            }
        }
        if (lane == 0) {
#pragma unroll
            for (int nt = 0; nt < 8; ++nt) {
                atomicAdd(&shst[2 * nt], ls[nt]);
                atomicAdd(&shst[2 * nt + 1], lss[nt]);
            }
        }
        __syncthreads();
        if (tid < 16) atomicAdd(&g_stats2[tid], shst[tid]);

        // ---- fused skip path: own-row GEMM vs g_ws -> g_skipf16 ----
        CP_WAIT(0);
        __syncthreads();
        const uint32_t Ab = base0;
        const uint32_t Bb = base0 + 16384u;
#pragma unroll
        for (int s = 0; s < 2; ++s)
#pragma unroll
            for (int i = 0; i < 8; ++i)
#pragma unroll
                for (int j = 0; j < 4; ++j) acc[s][i][j] = 0.f;

        uint32_t a[2][2][4];
#pragma unroll
        for (int s = 0; s < 2; ++s) {
            const int ar = arow0 + s * 16;
#pragma unroll
            for (int kc = 0; kc < 2; ++kc)
                ldsm4(a[s][kc], Ab + (uint32_t)ar * 64 +
                                ((((uint32_t)kc * 2 + asel) ^ ((uint32_t)ar & 3)) << 4));
        }
#pragma unroll
        for (int nt = 0; nt < 8; ++nt) {
#pragma unroll
            for (int kc = 0; kc < 2; ++kc) {
                uint32_t b2[2];
                ldsm2(b2, Bb + (uint32_t)nt * 512 + (uint32_t)brow * 64 +
                              ((((uint32_t)kc * 2 + bsel) ^ ((uint32_t)brow & 3)) << 4));
                mma16816(acc[0][nt], a[0][kc], b2);
                mma16816(acc[1][nt], a[1][kc], b2);
            }
        }
#pragma unroll
        for (int s = 0; s < 2; ++s) {
            const int row0 = v0 + w * 32 + s * 16 + g;
#pragma unroll
            for (int half = 0; half < 2; ++half) {
                int v = row0 + half * 8;
                if (v < n) {
                    __half* po = g_skipf16 + (size_t)v * 64;
#pragma unroll
                    for (int nt = 0; nt < 8; ++nt) {
                        int c = nt * 8 + tg * 2;
                        __half2 hh = __floats2half2_rn(
                            acc[s][nt][half * 2 + 0] + sskb[c],
                            acc[s][nt][half * 2 + 1] + sskb[c + 1]);
                        *(uint32_t*)(po + c) = *(uint32_t*)&hh;
                    }
                }
            }
        }
    }
}

__global__ void fill_tail_kernel(float* out, long start, long end) {
    long i = start + (long)blockIdx.x * blockDim.x + threadIdx.x;
    if (i < end) out[i] = 0.f;
}

// ---------------------------------------------------------------------------
extern "C" void kernel_launch(void* const* d_in, const int* in_sizes, int n_in,
                              void* d_out, int out_size) {
    const float* x      = (const float*)d_in[0];
    const int*   nbr    = (const int*)d_in[1];
    const float* gamma1 = (const float*)d_in[2];
    const float* beta1  = (const float*)d_in[3];
    const float* W1     = (const float*)d_in[4];
    const float* gamma2 = (const float*)d_in[5];
    const float* beta2  = (const float*)d_in[6];
    const float* W2     = (const float*)d_in[7];
    const float* Wskip  = (const float*)d_in[8];
    const float* bskip  = (const float*)d_in[9];
    float* out = (float*)d_out;

    int n = in_sizes[0] / 32;
    int nblk_mma = (n + 255) / 256;

    __half *xf16p = nullptr, *h1p = nullptr, *skp = nullptr,
           *w1p = nullptr, *w2p = nullptr, *wsp = nullptr;
    float *b1p = nullptr, *b2p = nullptr;
    cudaGetSymbolAddress((void**)&xf16p, g_xf16);
    cudaGetSymbolAddress((void**)&h1p, g_h1f16);
    cudaGetSymbolAddress((void**)&skp, g_skipf16);
    cudaGetSymbolAddress((void**)&w1p, g_w1);
    cudaGetSymbolAddress((void**)&w2p, g_w2);
    cudaGetSymbolAddress((void**)&wsp, g_ws);
    cudaGetSymbolAddress((void**)&b1p, g_bias1);
    cudaGetSymbolAddress((void**)&b2p, g_bias2);

    const int IDXB = 28672;
    const int SMEM1 = 1024 + IDXB + 4 * (16384 + 4096);  // 111616
    const int SMEM2 = 1024 + IDXB + 2 * (32768 + 8192);  // 111616
    cudaFuncSetAttribute(mma_conv_kernel<false>,
                         cudaFuncAttributeMaxDynamicSharedMemorySize, SMEM1);
    cudaFuncSetAttribute(mma_conv_kernel<true>,
                         cudaFuncAttributeMaxDynamicSharedMemorySize, SMEM2);

    // fused GN1 stats + x fp16 conversion
    zero_all_kernel<<<1, 160>>>();
    gn1_prep_kernel<<<1184, 256>>>(x, n);
    // W1 prep (inline GN1 finalize) + Wskip transpose (extra block)
    prepW1_kernel<<<KT + 1, 256>>>(W1, Wskip, gamma1, beta1, n);

    // conv1 -> g_h1f16 (fp16, post-SiLU) + fused skip path -> g_skipf16;
    // epilogue accumulates GN2 stats
    mma_conv_kernel<false><<<nblk_mma, 256, SMEM1>>>(
        xf16p, nbr, w1p, b1p, nullptr, wsp, bskip, (void*)h1p, n);

    // W2 prep (inline GN2 finalize)
    prepW2_kernel<<<KT, 256>>>(W2, gamma2, beta2, n);

    // conv2 -> out = silu(conv2) + skip
    mma_conv_kernel<true><<<nblk_mma, 256, SMEM2>>>(
        h1p, nbr, w2p, b2p, skp, nullptr, nullptr, (void*)out, n);

    long main_elems = (long)n * 64;
    if ((long)out_size > main_elems) {
        long tail = (long)out_size - main_elems;
        int tb = (int)((tail + 255) / 256);
        fill_tail_kernel<<<tb, 256>>>(out, main_elems, (long)out_size);
    }
}